// round 9
// baseline (speedup 1.0000x reference)
#include <cuda_runtime.h>
#include <cuda_fp16.h>

// Correlation: out[b, di*9+dj, y, x] = (1/64) * sum_c f1[b,c,y,x] * f2pad[b,c,y+di,x+dj]
// f1,f2: [4,64,192,448] f32; out: [4,81,192,448] f32; D=4.
//
// R8 champion structure (115.5us) + fp16 f2:
//  - pre-pass converts f2 -> zero-padded fp16 scratch [4][64][200][456]
//  - main kernel window loads are 12 halves (3x LDS.64, 96B-padded rows: ideal banking)
//  - f1 stays fp32; FMA loop and 4-deep cp.async ring unchanged; 16-stage full unroll.

#define D    4
#define CC   64
#define HH   192
#define WW   448
#define BB   4
#define XT   32
#define YT   4
#define XPT  4
#define NTX  8
#define NDJ  9
#define NDI  9
#define PW   (XT + 2*D)      // 40 halves of real data per row
#define PWS  48              // padded smem row (96 B) for ideal banking
#define PH   (YT + 2*D)      // 12
#define CS   4               // channels per stage
#define NSTAGE (CC / CS)     // 16
#define NTHREADS (NTX * YT * NDI)  // 288
#define RING 4

#define PH2  (HH + 2*D)      // 200
#define PW2  (WW + 2*D)      // 456 (row = 912 B, 16B-aligned)

#define F2S_BYTES  (CS*PH*PWS*2)          // 4608
#define STAGE_BYTES (F2S_BYTES + CS*YT*XT*4)  // 6656
#define STAGE_FLOATS (STAGE_BYTES/4)

#define NCH_F2 (CS*PH*(PW/8))   // 240 16B chunks (8 halves each)
#define NCH_F1 (CS*YT*(XT/4))   // 128 16B chunks (4 floats each)
#define NCH    (NCH_F2 + NCH_F1) // 368 = 288 + 80

// fp16 padded copy of f2: [B][C][PH2][PW2]
__device__ __align__(16) __half g2h[(size_t)BB * CC * PH2 * PW2];

__global__ __launch_bounds__(256)
void cvt_kernel(const float* __restrict__ f2)
{
    const int total = BB * CC * PH2 * PW2;   // 23,347,200
    int idx = blockIdx.x * 256 + threadIdx.x;
    if (idx >= total) return;
    const int px = idx % PW2;
    const int t  = idx / PW2;
    const int py = t % PH2;
    const int bc = t / PH2;
    const int gx = px - D;
    const int gy = py - D;
    float v = 0.f;
    if ((unsigned)gx < WW && (unsigned)gy < HH)
        v = f2[(size_t)bc * HH * WW + (size_t)gy * WW + gx];
    g2h[idx] = __float2half(v);
}

__device__ __forceinline__ void cp_async16(unsigned saddr, const void* gaddr) {
    asm volatile("cp.async.cg.shared.global [%0], [%1], 16;"
                 :: "r"(saddr), "l"(gaddr));
}

__global__ __launch_bounds__(NTHREADS, 3)
void corr_kernel(const float* __restrict__ f1,
                 float* __restrict__ out)
{
    __shared__ char smem[RING * STAGE_BYTES];   // 26624 B

    const int tx  = threadIdx.x;   // 0..7
    const int ty  = threadIdx.y;   // 0..3
    const int di  = threadIdx.z;   // 0..8
    const int tid = (di * YT + ty) * NTX + tx;

    const int x0 = blockIdx.x * XT;
    const int y0 = blockIdx.y * YT;
    const int b  = blockIdx.z;
    const int y  = y0 + ty;
    const int xp = tx * XPT;

    const float* f1b0 = f1 + (size_t)b * CC * HH * WW;
    const unsigned sbase = (unsigned)__cvta_generic_to_shared(smem);

    // ---- precompute cp.async chunks: chunk0 for all threads, chunk1 for tid<80
    const char* gbase[2];
    unsigned    gstr[2];
    unsigned    soff[2];
    const bool  has2 = (tid < NCH - NTHREADS);   // tid < 80
#pragma unroll
    for (int k = 0; k < 2; k++) {
        const int c = tid + k * NTHREADS;
        if (c < NCH_F2) {
            const int cc  = c / (PH * (PW/8));
            const int rem = c - cc * (PH * (PW/8));
            const int r   = rem / (PW/8);
            const int h   = rem - r * (PW/8);
            // padded scratch: px = gx + D, so gx = x0-4+8h -> px = x0+8h (16B aligned)
            gbase[k] = (const char*)g2h
                     + 2 * ((size_t)(b * CC + cc) * PH2 * PW2
                            + (size_t)(y0 + r) * PW2 + x0 + 8 * h);
            gstr[k]  = CS * PH2 * PW2 * 2;   // 729600
            soff[k]  = (cc * PH + r) * (PWS * 2) + 16 * h;
        } else {
            const int c2  = c - NCH_F2;
            const int cc  = c2 / (YT * (XT/4));
            const int rem = c2 - cc * (YT * (XT/4));
            const int r   = rem / (XT/4);
            const int h   = rem - r * (XT/4);
            gbase[k] = (const char*)(f1b0 + (size_t)cc * HH * WW
                                     + (size_t)(y0 + r) * WW + x0 + 4 * h);
            gstr[k]  = CS * HH * WW * 4;
            soff[k]  = F2S_BYTES + ((cc * YT + r) * XT + 4 * h) * 4;
        }
    }

    auto prefetch = [&](int s) {
        if (s < NSTAGE) {
            const unsigned sb = sbase + (s & (RING - 1)) * STAGE_BYTES;
            const size_t gadd = (size_t)s;
            cp_async16(sb + soff[0], gbase[0] + gadd * gstr[0]);
            if (has2) cp_async16(sb + soff[1], gbase[1] + gadd * gstr[1]);
        }
        asm volatile("cp.async.commit_group;" ::: "memory");
    };

    float acc[NDJ][XPT];
#pragma unroll
    for (int dj = 0; dj < NDJ; dj++)
#pragma unroll
        for (int xx = 0; xx < XPT; xx++) acc[dj][xx] = 0.f;

    prefetch(0);
    prefetch(1);
    prefetch(2);

#pragma unroll
    for (int s = 0; s < NSTAGE; s++) {
        asm volatile("cp.async.wait_group 2;" ::: "memory");
        __syncthreads();

        const char* stg = smem + (s & (RING - 1)) * STAGE_BYTES;

#pragma unroll
        for (int cc = 0; cc < CS; cc++) {
            const float4 v1 = *(const float4*)(stg + F2S_BYTES
                                + ((cc * YT + ty) * XT + xp) * 4);

            const __half* wrow = (const __half*)(stg + (cc * PH + ty + di) * (PWS * 2)) + xp;
            const uint2 ha = *(const uint2*)(wrow);       // halves 0..3
            const uint2 hb = *(const uint2*)(wrow + 4);   // halves 4..7
            const uint2 hc = *(const uint2*)(wrow + 8);   // halves 8..11

            float w[12];
            {
                float2 p;
                p = __half22float2(*(const __half2*)&ha.x); w[0] = p.x; w[1]  = p.y;
                p = __half22float2(*(const __half2*)&ha.y); w[2] = p.x; w[3]  = p.y;
                p = __half22float2(*(const __half2*)&hb.x); w[4] = p.x; w[5]  = p.y;
                p = __half22float2(*(const __half2*)&hb.y); w[6] = p.x; w[7]  = p.y;
                p = __half22float2(*(const __half2*)&hc.x); w[8] = p.x; w[9]  = p.y;
                p = __half22float2(*(const __half2*)&hc.y); w[10] = p.x; w[11] = p.y;
            }

#pragma unroll
            for (int dj = 0; dj < NDJ; dj++) {
                acc[dj][0] += v1.x * w[dj + 0];
                acc[dj][1] += v1.y * w[dj + 1];
                acc[dj][2] += v1.z * w[dj + 2];
                acc[dj][3] += v1.w * w[dj + 3];
            }
        }
        // Prefetch at END of compute (measured best): stage s+3 lands in buffer
        // (s-1)&3, fully consumed before this stage's barrier.
        prefetch(s + 3);
    }

    const float scale = 1.f / (float)CC;
    float* ob = out + (((size_t)b * (NDI * NDJ) + di * NDJ) * HH + y) * WW + x0 + xp;
#pragma unroll
    for (int dj = 0; dj < NDJ; dj++) {
        float4 o;
        o.x = acc[dj][0] * scale;
        o.y = acc[dj][1] * scale;
        o.z = acc[dj][2] * scale;
        o.w = acc[dj][3] * scale;
        *(float4*)&ob[(size_t)dj * HH * WW] = o;
    }
}

extern "C" void kernel_launch(void* const* d_in, const int* in_sizes, int n_in,
                              void* d_out, int out_size)
{
    const float* f1 = (const float*)d_in[0];
    const float* f2 = (const float*)d_in[1];
    float* out = (float*)d_out;

    const int total = BB * CC * PH2 * PW2;
    cvt_kernel<<<(total + 255) / 256, 256>>>(f2);

    dim3 grid(WW / XT, HH / YT, BB);   // 14 x 48 x 4 = 2688 CTAs
    dim3 block(NTX, YT, NDI);          // 288 threads
    corr_kernel<<<grid, block>>>(f1, out);
}